// round 4
// baseline (speedup 1.0000x reference)
#include <cuda_runtime.h>
#include <math_constants.h>

// Problem maxima (fixed by the dataset): B=4, N=20000, E=640000, H=8
#define MAXB 4
#define MAXN 20000
#define MAXE 640000

// Scratch (device globals; no dynamic allocation allowed)
__device__ float g_x0 [MAXB * MAXN * 3];   // raw node inputs [B*N,3]
__device__ float g_pd [MAXB * MAXN * 8];   // per-node projection for dst role
__device__ float g_ps [MAXB * MAXN * 8];   // per-node projection for src role
__device__ float g_agg[MAXB * MAXN * 8];   // scatter-min buffer (+inf init)
__device__ int   g_src[MAXB * MAXE];       // src node (with b*N offset baked in)
__device__ int   g_dst[MAXB * MAXE];       // dst node (with b*N offset baked in)
__device__ float g_pool[MAXB * 11];        // per-graph pooled sums

__device__ __forceinline__ float lrelu(float x) { return fmaxf(x, 0.01f * x); }

// Bit-exact +inf -> 0 (immune to fast-math eliding isfinite)
__device__ __forceinline__ float inf_to_zero(float v) {
    return (__float_as_uint(v) == 0x7f800000u) ? 0.0f : v;
}

// float atomic-min via int-min (nonneg) / uint-max (neg). Valid with +inf init.
__device__ __forceinline__ void atomicMinF(float* a, float v) {
    if (v >= 0.0f) atomicMin((int*)a,          __float_as_int(v));
    else           atomicMax((unsigned int*)a, __float_as_uint(v));
}

// ---------------------------------------------------------------------------
// K0: build x0, layer-1 node projections (input dim 3), init agg, zero pool
// ---------------------------------------------------------------------------
__global__ void k_prep(const int* __restrict__ nf, const float* __restrict__ act,
                       const float* __restrict__ W1, int BN) {
    int i = blockIdx.x * blockDim.x + threadIdx.x;
    if (i < MAXB * 11) g_pool[i] = 0.0f;
    if (i >= BN) return;
    float x0 = (float)nf[2 * i];
    float x1 = (float)nf[2 * i + 1];
    float x2 = act[i];
    g_x0[3 * i]     = x0;
    g_x0[3 * i + 1] = x1;
    g_x0[3 * i + 2] = x2;
#pragma unroll
    for (int j = 0; j < 8; j++) {
        // W1 rows 0..2 -> x_dst part, rows 3..5 -> x_src part (row 6 = edge attr)
        g_pd[8 * i + j] = fmaf(x0, __ldg(W1 + 0 * 8 + j),
                          fmaf(x1, __ldg(W1 + 1 * 8 + j),
                               x2 * __ldg(W1 + 2 * 8 + j)));
        g_ps[8 * i + j] = fmaf(x0, __ldg(W1 + 3 * 8 + j),
                          fmaf(x1, __ldg(W1 + 4 * 8 + j),
                               x2 * __ldg(W1 + 5 * 8 + j)));
        g_agg[8 * i + j] = CUDART_INF_F;
    }
}

// ---------------------------------------------------------------------------
// K1: edge_index (int32 — JAX demotes int64 without x64) -> per-graph offset
// baked in, split into src/dst arrays. Layout: [B, 2, E].
// ---------------------------------------------------------------------------
__global__ void k_conv(const int* __restrict__ ei, int B, int E, int N) {
    int i = blockIdx.x * blockDim.x + threadIdx.x;
    int total = B * 2 * E;
    if (i >= total) return;
    int b = i / (2 * E);
    int r = (i / E) & 1;
    int k = i - b * 2 * E - r * E;
    int v = ei[i] + b * N;
    if (r == 0) g_src[b * E + k] = v;
    else        g_dst[b * E + k] = v;
}

// ---------------------------------------------------------------------------
// K2 (x3): per-edge MLP + scatter-min at dst. Layer-agnostic: consumes
// precomputed node projections g_pd/g_ps, c = edge-attr row of W1.
// ---------------------------------------------------------------------------
__global__ void k_edge(const float* __restrict__ ea,
                       const float* __restrict__ crow,
                       const float* __restrict__ b1,
                       const float* __restrict__ W2,
                       const float* __restrict__ b2,
                       int total) {
    float c[8], B1[8], B2[8], w2[64];
#pragma unroll
    for (int j = 0; j < 8; j++) {
        c[j]  = __ldg(crow + j);
        B1[j] = __ldg(b1 + j);
        B2[j] = __ldg(b2 + j);
    }
#pragma unroll
    for (int j = 0; j < 64; j++) w2[j] = __ldg(W2 + j);

    int stride = blockDim.x * gridDim.x;
    for (int e = blockIdx.x * blockDim.x + threadIdx.x; e < total; e += stride) {
        int s = g_src[e];
        int d = g_dst[e];
        float eav = __ldg(ea + e);

        float pdv[8], psv[8];
        *(float4*)&pdv[0] = *(const float4*)(g_pd + 8 * d);
        *(float4*)&pdv[4] = *(const float4*)(g_pd + 8 * d + 4);
        *(float4*)&psv[0] = *(const float4*)(g_ps + 8 * s);
        *(float4*)&psv[4] = *(const float4*)(g_ps + 8 * s + 4);

        float hid[8];
#pragma unroll
        for (int j = 0; j < 8; j++)
            hid[j] = lrelu(pdv[j] + psv[j] + fmaf(c[j], eav, B1[j]));

#pragma unroll
        for (int j = 0; j < 8; j++) {
            float o = B2[j];
#pragma unroll
            for (int k = 0; k < 8; k++) o = fmaf(hid[k], w2[k * 8 + j], o);
            atomicMinF(&g_agg[8 * d + j], o);
        }
    }
}

// ---------------------------------------------------------------------------
// K3 (x2): node update h = lrelu(inf->0(agg)); compute next-layer projections
// (W1next rows 0..7 dst part, 8..15 src part); reset agg to +inf
// ---------------------------------------------------------------------------
__global__ void k_node(const float* __restrict__ W1n, int BN) {
    int i = blockIdx.x * blockDim.x + threadIdx.x;
    if (i >= BN) return;
    float h[8];
#pragma unroll
    for (int j = 0; j < 8; j++) {
        float v = inf_to_zero(g_agg[8 * i + j]);
        h[j] = lrelu(v);
        g_agg[8 * i + j] = CUDART_INF_F;
    }
#pragma unroll
    for (int j = 0; j < 8; j++) {
        float a = 0.0f, b = 0.0f;
#pragma unroll
        for (int k = 0; k < 8; k++) {
            a = fmaf(h[k], __ldg(W1n + k * 8 + j), a);
            b = fmaf(h[k], __ldg(W1n + (8 + k) * 8 + j), b);
        }
        g_pd[8 * i + j] = a;
        g_ps[8 * i + j] = b;
    }
}

// ---------------------------------------------------------------------------
// K4: final node update + sum-pool of [x0, h3] into g_pool (11 per graph)
// ---------------------------------------------------------------------------
__global__ void k_final(int BN, int N) {
    __shared__ float s[2][11];  // a block can straddle at most 2 graphs
    int t = threadIdx.x;
    if (t < 22) ((float*)s)[t] = 0.0f;
    __syncthreads();

    int i  = blockIdx.x * blockDim.x + t;
    int b0 = (blockIdx.x * blockDim.x) / N;
    int B  = BN / N;
    if (i < BN) {
        int b = i / N;
        int slot = b - b0;
        float vals[11];
        vals[0] = g_x0[3 * i];
        vals[1] = g_x0[3 * i + 1];
        vals[2] = g_x0[3 * i + 2];
#pragma unroll
        for (int j = 0; j < 8; j++) {
            float v = inf_to_zero(g_agg[8 * i + j]);
            vals[3 + j] = lrelu(v);
        }
#pragma unroll
        for (int cc = 0; cc < 11; cc++) atomicAdd(&s[slot][cc], vals[cc]);
    }
    __syncthreads();
    if (t < 22) {
        int slot = t / 11, cc = t - slot * 11;
        int b = b0 + slot;
        if (b < B) atomicAdd(&g_pool[b * 11 + cc], s[slot][cc]);
    }
}

// ---------------------------------------------------------------------------
// K5: final linear  out[b] = pool[b] . lin_W + lin_b
// ---------------------------------------------------------------------------
__global__ void k_out(const float* __restrict__ linW, const float* __restrict__ linb,
                      float* __restrict__ out, int B) {
    int b = threadIdx.x;
    if (b < B) {
        float acc = __ldg(linb);
#pragma unroll
        for (int k = 0; k < 11; k++) acc = fmaf(g_pool[b * 11 + k], __ldg(linW + k), acc);
        out[b] = acc;
    }
}

extern "C" void kernel_launch(void* const* d_in, const int* in_sizes, int n_in,
                              void* d_out, int out_size) {
    const int*   nf   = (const int*)d_in[0];
    const float* act  = (const float*)d_in[1];
    const int*   ei   = (const int*)d_in[2];   // int32 (JAX x64 disabled)
    const float* ea   = (const float*)d_in[3];
    const float* c1W1 = (const float*)d_in[4];
    const float* c1b1 = (const float*)d_in[5];
    const float* c1W2 = (const float*)d_in[6];
    const float* c1b2 = (const float*)d_in[7];
    const float* c2W1 = (const float*)d_in[8];
    const float* c2b1 = (const float*)d_in[9];
    const float* c2W2 = (const float*)d_in[10];
    const float* c2b2 = (const float*)d_in[11];
    const float* c3W1 = (const float*)d_in[12];
    const float* c3b1 = (const float*)d_in[13];
    const float* c3W2 = (const float*)d_in[14];
    const float* c3b2 = (const float*)d_in[15];
    const float* linW = (const float*)d_in[16];
    const float* linb = (const float*)d_in[17];

    int B  = out_size;         // 4
    int BN = in_sizes[1];      // B*N = 80000
    int N  = BN / B;           // 20000
    int BE = in_sizes[3];      // B*E = 2560000
    int E  = BE / B;           // 640000

    int nb_node = (BN + 255) / 256;
    int nb_conv = (B * 2 * E + 255) / 256;
    int nb_edge = (BE + 1023) / 1024;   // 4 edges per thread via grid-stride

    k_prep<<<nb_node, 256>>>(nf, act, c1W1, BN);
    k_conv<<<nb_conv, 256>>>(ei, B, E, N);

    // layer 1 (input dim 3: edge-attr row = W1[6])
    k_edge<<<nb_edge, 256>>>(ea, c1W1 + 6 * 8, c1b1, c1W2, c1b2, BE);
    k_node<<<nb_node, 256>>>(c2W1, BN);
    // layer 2 (input dim 8: edge-attr row = W1[16])
    k_edge<<<nb_edge, 256>>>(ea, c2W1 + 16 * 8, c2b1, c2W2, c2b2, BE);
    k_node<<<nb_node, 256>>>(c3W1, BN);
    // layer 3
    k_edge<<<nb_edge, 256>>>(ea, c3W1 + 16 * 8, c3b1, c3W2, c3b2, BE);

    k_final<<<nb_node, 256>>>(BN, N);
    k_out<<<1, 32>>>(linW, linb, (float*)d_out, B);
}